// round 3
// baseline (speedup 1.0000x reference)
#include <cuda_runtime.h>
#include <cuda_fp16.h>
#include <cstdint>

// ---------------------------------------------------------------------------
// Seq2Seq RNN (tanh), B=1024, T=128, H=512, L=4, PRED_LEN=10.
// Round 3: persistent encoder (131 anti-diagonals in one kernel, software grid
// barrier) + persistent decoder (40 steps + FC head in one kernel), and
// register-cached mma fragments (6 ldsm / kk instead of 9).
// Split-fp16 (hi/lo, 3 products) tensor-core GEMM, fp32 accumulate.
// ---------------------------------------------------------------------------

#define ACT_L 67108864LL  // halves per (layer, hi/lo) activation plane

static __device__ __half g_act[8LL * ACT_L];     // [4 layers][2 hi/lo][1024*128*512]
static __device__ __half g_wenc_hi[2097152];     // [4][1024 k][512 n]
static __device__ __half g_wenc_lo[2097152];
static __device__ __half g_wdec_hi[2097152];
static __device__ __half g_wdec_lo[2097152];
static __device__ __half g_dh_hi[4194304];       // [2][4][1024][512]
static __device__ __half g_dh_lo[4194304];
static __device__ float  g_decout[5242880];      // [1024][10][512]
static __device__ unsigned g_bar_enc;
static __device__ unsigned g_bar_dec;

__device__ __forceinline__ uint32_t smem_u32(const void* p) {
    return (uint32_t)__cvta_generic_to_shared(p);
}

__device__ __forceinline__ void cp16(uint32_t saddr, const void* g) {
    asm volatile("cp.async.cg.shared.global [%0], [%1], 16;\n" :: "r"(saddr), "l"(g));
}

__device__ __forceinline__ void mma16816(float* c,
                                         uint32_t a0, uint32_t a1, uint32_t a2, uint32_t a3,
                                         uint32_t b0, uint32_t b1) {
    asm volatile(
        "mma.sync.aligned.m16n8k16.row.col.f32.f16.f16.f32 "
        "{%0,%1,%2,%3}, {%4,%5,%6,%7}, {%8,%9}, {%0,%1,%2,%3};"
        : "+f"(c[0]), "+f"(c[1]), "+f"(c[2]), "+f"(c[3])
        : "r"(a0), "r"(a1), "r"(a2), "r"(a3), "r"(b0), "r"(b1));
}

__device__ __forceinline__ void ldsm_x4(uint32_t addr, uint32_t& r0, uint32_t& r1,
                                        uint32_t& r2, uint32_t& r3) {
    asm volatile("ldmatrix.sync.aligned.m8n8.x4.shared.b16 {%0,%1,%2,%3}, [%4];"
                 : "=r"(r0), "=r"(r1), "=r"(r2), "=r"(r3) : "r"(addr));
}

__device__ __forceinline__ void ldsm_x4_t(uint32_t addr, uint32_t& r0, uint32_t& r1,
                                          uint32_t& r2, uint32_t& r3) {
    asm volatile("ldmatrix.sync.aligned.m8n8.x4.trans.shared.b16 {%0,%1,%2,%3}, [%4];"
                 : "=r"(r0), "=r"(r1), "=r"(r2), "=r"(r3) : "r"(addr));
}

// Monotonic-counter grid barrier (all CTAs resident; target = gen * gridDim.x).
__device__ __forceinline__ void grid_barrier(unsigned* bar, unsigned target) {
    __syncthreads();
    if (threadIdx.x == 0) {
        __threadfence();
        atomicAdd(bar, 1u);
        unsigned v;
        for (;;) {
            asm volatile("ld.acquire.gpu.u32 %0, [%1];" : "=r"(v) : "l"(bar));
            if (v >= target) break;
            __nanosleep(64);
        }
    }
    __syncthreads();
}

struct __align__(16) Smem {
    __half A[2][2][64][40];   // [buf][hi/lo][m][k]
    __half B[2][2][32][72];   // [buf][hi/lo][k][n]
};

// out = tanh(X@Wih^T + H@Whh^T + bih + bhh), split-fp16 3-product GEMM.
// Weight k rows [0,512) are the X part, [512,1024) the H part.
__device__ __forceinline__ void step_core(
    Smem& sm, int bm0, int bn0,
    const __half* __restrict__ Xhi, const __half* __restrict__ Xlo, long long ldx,
    const __half* __restrict__ Hhi, const __half* __restrict__ Hlo, long long ldh,
    const __half* __restrict__ Whi, const __half* __restrict__ Wlo,
    const float* __restrict__ bih, const float* __restrict__ bhh,
    __half* __restrict__ outHi, __half* __restrict__ outLo, long long ldoh,
    float* __restrict__ out32, long long ldo32,
    int kstart, int kend,
    const float* __restrict__ Xraw, long long ldxraw, const float* __restrict__ Wih0)
{
    const int tid = threadIdx.x;
    const int lane = tid & 31;
    const int warp = tid >> 5;
    const int wm = (warp & 3) * 16;
    const int wn = (warp >> 2) * 32;

    float acc[4][4];
#pragma unroll
    for (int i = 0; i < 4; ++i)
#pragma unroll
        for (int j = 0; j < 4; ++j) acc[i][j] = 0.f;

    if (Xraw) {  // layer-0 tiny input projection (K=6), direct fp32
        const int mlo = bm0 + wm + (lane >> 2);
        float xr[2][6];
#pragma unroll
        for (int r = 0; r < 2; ++r)
#pragma unroll
            for (int k = 0; k < 6; ++k)
                xr[r][k] = Xraw[(long long)(mlo + r * 8) * ldxraw + k];
#pragma unroll
        for (int nt = 0; nt < 4; ++nt)
#pragma unroll
            for (int j = 0; j < 2; ++j) {
                const int gn = bn0 + wn + nt * 8 + (lane & 3) * 2 + j;
#pragma unroll
                for (int k = 0; k < 6; ++k) {
                    const float w = Wih0[gn * 6 + k];
                    acc[nt][j]     += xr[0][k] * w;
                    acc[nt][2 + j] += xr[1][k] * w;
                }
            }
    }

    const int nkb = (kend - kstart) >> 5;
    const int arow = tid >> 2, aq = (tid & 3) * 8;
    const int brow = tid >> 3, bq = (tid & 7) * 8;

    auto issue = [&](int kb) {
        const int k0 = kstart + kb * 32;
        const int buf = kb & 1;
        const __half *ah, *al;
        long long la;
        int kk;
        if (k0 < 512) { ah = Xhi; al = Xlo; la = ldx; kk = k0; }
        else          { ah = Hhi; al = Hlo; la = ldh; kk = k0 - 512; }
        const long long aoff = (long long)(bm0 + arow) * la + kk + aq;
        cp16(smem_u32(&sm.A[buf][0][arow][aq]), ah + aoff);
        cp16(smem_u32(&sm.A[buf][1][arow][aq]), al + aoff);
        const long long boff = (long long)(k0 + brow) * 512 + bn0 + bq;
        cp16(smem_u32(&sm.B[buf][0][brow][bq]), Whi + boff);
        cp16(smem_u32(&sm.B[buf][1][brow][bq]), Wlo + boff);
    };

    if (nkb > 0) {
        issue(0);
        asm volatile("cp.async.commit_group;\n" ::: "memory");
        for (int kb = 0; kb < nkb; ++kb) {
            if (kb + 1 < nkb) issue(kb + 1);
            asm volatile("cp.async.commit_group;\n" ::: "memory");
            asm volatile("cp.async.wait_group 1;\n" ::: "memory");
            __syncthreads();
            const int buf = kb & 1;
#pragma unroll
            for (int kk = 0; kk < 32; kk += 16) {
                // load A hi/lo fragments once
                uint32_t ah0, ah1, ah2, ah3, al0, al1, al2, al3;
                const int ar = wm + (lane & 15);
                const int ac = kk + ((lane >> 4) << 3);
                ldsm_x4(smem_u32(&sm.A[buf][0][ar][ac]), ah0, ah1, ah2, ah3);
                ldsm_x4(smem_u32(&sm.A[buf][1][ar][ac]), al0, al1, al2, al3);
#pragma unroll
                for (int pair = 0; pair < 2; ++pair) {
                    const int nb = wn + pair * 16;
                    const int br = kk + (lane & 7) + (((lane >> 3) & 1) << 3);
                    const int bc = nb + ((lane >> 4) << 3);
                    uint32_t bh0, bh1, bh2, bh3, bl0, bl1, bl2, bl3;
                    ldsm_x4_t(smem_u32(&sm.B[buf][0][br][bc]), bh0, bh1, bh2, bh3);
                    ldsm_x4_t(smem_u32(&sm.B[buf][1][br][bc]), bl0, bl1, bl2, bl3);
                    float* c0 = acc[pair * 2 + 0];
                    float* c1 = acc[pair * 2 + 1];
                    mma16816(c0, ah0, ah1, ah2, ah3, bh0, bh1);
                    mma16816(c1, ah0, ah1, ah2, ah3, bh2, bh3);
                    mma16816(c0, al0, al1, al2, al3, bh0, bh1);
                    mma16816(c1, al0, al1, al2, al3, bh2, bh3);
                    mma16816(c0, ah0, ah1, ah2, ah3, bl0, bl1);
                    mma16816(c1, ah0, ah1, ah2, ah3, bl2, bl3);
                }
            }
            __syncthreads();
        }
    }

    // epilogue: bias + tanh + producer-side split write (+ optional fp32 write)
#pragma unroll
    for (int nt = 0; nt < 4; ++nt)
#pragma unroll
        for (int i = 0; i < 2; ++i)
#pragma unroll
            for (int j = 0; j < 2; ++j) {
                const int m = bm0 + wm + (lane >> 2) + i * 8;
                const int gn = bn0 + wn + nt * 8 + (lane & 3) * 2 + j;
                const float v = tanhf(acc[nt][i * 2 + j] + bih[gn] + bhh[gn]);
                const __half hi = __float2half_rn(v);
                const __half lo = __float2half_rn(v - __half2float(hi));
                outHi[(long long)m * ldoh + gn] = hi;
                outLo[(long long)m * ldoh + gn] = lo;
                if (out32) out32[(long long)m * ldo32 + gn] = v;
            }
}

// Persistent encoder: all 131 anti-diagonals, grid barrier between diagonals.
__global__ void __launch_bounds__(256, 4) enc_persist_kernel(
    const float* __restrict__ xraw, const float* __restrict__ Wih0,
    const float* __restrict__ ebih, const float* __restrict__ ebhh,
    float* __restrict__ enc_out)
{
    __shared__ Smem sm;
    unsigned gen = 0;

    for (int d = 0; d < 131; ++d) {
        const int llo = (d > 127) ? d - 127 : 0;
        const int lhi = (d < 3) ? d : 3;
        const int ntiles = (lhi - llo + 1) << 7;

        for (int tile = blockIdx.x; tile < ntiles; tile += gridDim.x) {
            const int l = llo + (tile >> 7);
            const int t = d - l;
            const int tl = tile & 127;
            const int bm0 = (tl & 15) * 64;
            const int bn0 = (tl >> 4) * 64;

            const __half* Whi = g_wenc_hi + (long long)l * 524288;
            const __half* Wlo = g_wenc_lo + (long long)l * 524288;
            __half* actl_hi = g_act + ((long long)l * 2 + 0) * ACT_L;
            __half* actl_lo = g_act + ((long long)l * 2 + 1) * ACT_L;

            const __half *Xhi = nullptr, *Xlo = nullptr, *Hhi = nullptr, *Hlo = nullptr;
            long long ldx = 0;
            int kstart = 512, kend = 512;
            const float* Xr = nullptr;

            if (l == 0) {
                Xr = xraw + (long long)t * 6;
            } else {
                const __half* prev = g_act + ((long long)(l - 1) * 2) * ACT_L;
                Xhi = prev + (long long)t * 512;
                Xlo = prev + ACT_L + (long long)t * 512;
                ldx = 65536;
                kstart = 0;
            }
            if (t > 0) {
                Hhi = actl_hi + (long long)(t - 1) * 512;
                Hlo = actl_lo + (long long)(t - 1) * 512;
                kend = 1024;
            }
            float* o32 = (l == 3) ? enc_out + (long long)t * 512 : nullptr;

            step_core(sm, bm0, bn0, Xhi, Xlo, ldx, Hhi, Hlo, 65536,
                      Whi, Wlo, ebih + l * 512, ebhh + l * 512,
                      actl_hi + (long long)t * 512, actl_lo + (long long)t * 512,
                      65536, o32, 65536, kstart, kend, Xr, 768, Wih0);
        }
        ++gen;
        grid_barrier(&g_bar_enc, gen * gridDim.x);
    }
}

// Persistent decoder: 10 steps x 4 layers serial + FC head.
__global__ void __launch_bounds__(256, 4) dec_persist_kernel(
    const float* __restrict__ dbih, const float* __restrict__ dbhh,
    const float* __restrict__ fcW, const float* __restrict__ fcb,
    float* __restrict__ outputs)
{
    __shared__ Smem sm;
    unsigned gen = 0;
    const int tid = threadIdx.x;

    for (int s = 0; s < 10; ++s) {
        const int wset = s & 1;
        const int rset = (s - 1) & 1;
        for (int l = 0; l < 4; ++l) {
            const __half *Xhi, *Xlo, *Hhi, *Hlo;
            long long ldx, ldh;
            if (l == 0) {
                if (s == 0) {
                    Xhi = g_act + 6 * ACT_L + 127LL * 512;
                    Xlo = g_act + 7 * ACT_L + 127LL * 512;
                    ldx = 65536;
                } else {
                    Xhi = g_dh_hi + ((long long)rset * 4 + 3) * 524288;
                    Xlo = g_dh_lo + ((long long)rset * 4 + 3) * 524288;
                    ldx = 512;
                }
            } else {
                Xhi = g_dh_hi + ((long long)wset * 4 + (l - 1)) * 524288;
                Xlo = g_dh_lo + ((long long)wset * 4 + (l - 1)) * 524288;
                ldx = 512;
            }
            if (s == 0) {
                Hhi = g_act + ((long long)l * 2 + 0) * ACT_L + 127LL * 512;
                Hlo = g_act + ((long long)l * 2 + 1) * ACT_L + 127LL * 512;
                ldh = 65536;
            } else {
                Hhi = g_dh_hi + ((long long)rset * 4 + l) * 524288;
                Hlo = g_dh_lo + ((long long)rset * 4 + l) * 524288;
                ldh = 512;
            }
            __half* oHi = g_dh_hi + ((long long)wset * 4 + l) * 524288;
            __half* oLo = g_dh_lo + ((long long)wset * 4 + l) * 524288;
            float* o32 = (l == 3) ? g_decout + (long long)s * 512 : nullptr;

            for (int tile = blockIdx.x; tile < 128; tile += gridDim.x) {
                const int bm0 = (tile & 15) * 64;
                const int bn0 = (tile >> 4) * 64;
                step_core(sm, bm0, bn0, Xhi, Xlo, ldx, Hhi, Hlo, ldh,
                          g_wdec_hi + (long long)l * 524288,
                          g_wdec_lo + (long long)l * 524288,
                          dbih + l * 512, dbhh + l * 512,
                          oHi, oLo, 512, o32, 5120, 0, 1024,
                          nullptr, 0, nullptr);
            }
            ++gen;
            grid_barrier(&g_bar_dec, gen * gridDim.x);
        }
    }

    // FC head: outputs[r, n] = decout[r, :] @ fcW[n, :] + fcb[n]
    float* Ws = reinterpret_cast<float*>(&sm);
    for (int i = tid; i < 6 * 512; i += 256) Ws[i] = fcW[i];
    __syncthreads();

    const int lane = tid & 31;
    const int gw = blockIdx.x * 8 + (tid >> 5);
    for (int row = gw; row < 10240; row += gridDim.x * 8) {
        float p[6] = {0.f, 0.f, 0.f, 0.f, 0.f, 0.f};
        for (int k = lane; k < 512; k += 32) {
            const float v = g_decout[(long long)row * 512 + k];
#pragma unroll
            for (int n = 0; n < 6; ++n) p[n] += v * Ws[n * 512 + k];
        }
#pragma unroll
        for (int off = 16; off > 0; off >>= 1)
#pragma unroll
            for (int n = 0; n < 6; ++n)
                p[n] += __shfl_down_sync(0xffffffffu, p[n], off);
        if (lane == 0) {
#pragma unroll
            for (int n = 0; n < 6; ++n) out:;
        }
        if (lane == 0) {
#pragma unroll
            for (int n = 0; n < 6; ++n) outputs[(long long)row * 6 + n] = p[n] + fcb[n];
        }
    }
}

// Split + transpose all weights once; also reset barrier counters.
__global__ void __launch_bounds__(256) prep_kernel(
    const float* __restrict__ eWih, const float* __restrict__ eWhh,
    const float* __restrict__ dWih, const float* __restrict__ dWhh)
{
    if (blockIdx.x == 0 && threadIdx.x == 0) { g_bar_enc = 0; g_bar_dec = 0; }
    const long long idx = (long long)blockIdx.x * 256 + threadIdx.x;
    const long long total = 2097152;
    const int model = idx >= total;
    const long long j = idx - (long long)model * total;
    const int l = (int)(j >> 19);
    const int r = (int)((j >> 9) & 1023);
    const int n = (int)(j & 511);
    float v;
    if (!model) {
        if (r < 512) v = (l == 0) ? 0.f : eWih[(((long long)(l - 1) * 512 + n) << 9) + r];
        else         v = eWhh[(((long long)l * 512 + n) << 9) + (r - 512)];
    } else {
        if (r < 512) v = dWih[(((long long)l * 512 + n) << 9) + r];
        else         v = dWhh[(((long long)l * 512 + n) << 9) + (r - 512)];
    }
    const __half hi = __float2half_rn(v);
    const __half lo = __float2half_rn(v - __half2float(hi));
    if (!model) { g_wenc_hi[j] = hi; g_wenc_lo[j] = lo; }
    else        { g_wdec_hi[j] = hi; g_wdec_lo[j] = lo; }
}

extern "C" void kernel_launch(void* const* d_in, const int* in_sizes, int n_in,
                              void* d_out, int out_size) {
    const float* x     = (const float*)d_in[0];
    const float* eWih0 = (const float*)d_in[1];
    const float* eWih  = (const float*)d_in[2];
    const float* eWhh  = (const float*)d_in[3];
    const float* ebih  = (const float*)d_in[4];
    const float* ebhh  = (const float*)d_in[5];
    const float* dWih  = (const float*)d_in[6];
    const float* dWhh  = (const float*)d_in[7];
    const float* dbih  = (const float*)d_in[8];
    const float* dbhh  = (const float*)d_in[9];
    const float* fcW   = (const float*)d_in[10];
    const float* fcb   = (const float*)d_in[11];

    float* out = (float*)d_out;
    float* enc_out = out;               // [1024,128,512]
    float* outputs = out + 67108864LL;  // [1024,10,6]

    // Grid sizing: every CTA of a persistent kernel MUST be resident.
    static int enc_grid = 0, dec_grid = 0;
    if (enc_grid == 0) {
        cudaFuncSetAttribute(enc_persist_kernel,
                             cudaFuncAttributePreferredSharedMemoryCarveout, 100);
        cudaFuncSetAttribute(dec_persist_kernel,
                             cudaFuncAttributePreferredSharedMemoryCarveout, 100);
        int dev = 0, nsm = 148, nb = 1;
        cudaGetDevice(&dev);
        cudaDeviceGetAttribute(&nsm, cudaDevAttrMultiProcessorCount, dev);
        cudaOccupancyMaxActiveBlocksPerMultiprocessor(&nb, enc_persist_kernel, 256, 0);
        if (nb < 1) nb = 1;
        enc_grid = nb * nsm;
        if (enc_grid > 512) enc_grid = 512;
        int nbd = 1;
        cudaOccupancyMaxActiveBlocksPerMultiprocessor(&nbd, dec_persist_kernel, 256, 0);
        if (nbd < 1) nbd = 1;
        dec_grid = nbd * nsm;
        if (dec_grid > 128) dec_grid = 128;
    }

    prep_kernel<<<16384, 256>>>(eWih, eWhh, dWih, dWhh);
    enc_persist_kernel<<<enc_grid, 256>>>(x, eWih0, ebih, ebhh, enc_out);
    dec_persist_kernel<<<dec_grid, 256>>>(dbih, dbhh, fcW, fcb, outputs);
}